// round 9
// baseline (speedup 1.0000x reference)
#include <cuda_runtime.h>
#include <cuda_fp16.h>
#include <cstdint>

#define SEQ 2048
#define DM  1024
#define NB  2
#define NH  16
#define DHD 64

// 0.125 * log2(e)
#define QSCALE 0.1803368801111244f

// ---------------------------------------------------------------------------
// Scratch
// ---------------------------------------------------------------------------
__device__ __half g_qf[(size_t)NB * SEQ * DM];
__device__ __half g_kf[(size_t)NB * SEQ * DM];
__device__ __half g_vf[(size_t)NB * SEQ * DM];
__device__ __half g_Wqf[(size_t)DM * DM];
__device__ __half g_Wkf[(size_t)DM * DM];
__device__ __half g_Wvf[(size_t)DM * DM];
__device__ __half g_Wof[(size_t)DM * DM];
__device__ __half g_Qh[(size_t)NB * SEQ * DM];
__device__ __half g_Kh[(size_t)NB * SEQ * DM];
__device__ __half g_Vt[(size_t)NB * DM * SEQ];
__device__ __half g_Ah[(size_t)NB * SEQ * DM];

// ---------------------------------------------------------------------------
// PTX helpers
// ---------------------------------------------------------------------------
__device__ __forceinline__ uint32_t smem_u32(const void* p) {
    uint32_t a;
    asm("{ .reg .u64 t; cvta.to.shared.u64 t, %1; cvt.u32.u64 %0, t; }" : "=r"(a) : "l"(p));
    return a;
}
__device__ __forceinline__ void ldsm_x4(uint32_t& r0, uint32_t& r1, uint32_t& r2,
                                        uint32_t& r3, uint32_t addr) {
    asm volatile("ldmatrix.sync.aligned.m8n8.x4.shared.b16 {%0,%1,%2,%3}, [%4];"
                 : "=r"(r0), "=r"(r1), "=r"(r2), "=r"(r3) : "r"(addr));
}
__device__ __forceinline__ void mma16816(float* c, const uint32_t* a,
                                         uint32_t b0, uint32_t b1) {
    asm volatile(
        "mma.sync.aligned.m16n8k16.row.col.f32.f16.f16.f32 "
        "{%0,%1,%2,%3}, {%4,%5,%6,%7}, {%8,%9}, {%0,%1,%2,%3};"
        : "+f"(c[0]), "+f"(c[1]), "+f"(c[2]), "+f"(c[3])
        : "r"(a[0]), "r"(a[1]), "r"(a[2]), "r"(a[3]), "r"(b0), "r"(b1));
}
__device__ __forceinline__ void mma16816h(uint32_t* c, const uint32_t* a,
                                          uint32_t b0, uint32_t b1) {
    asm volatile(
        "mma.sync.aligned.m16n8k16.row.col.f16.f16.f16.f16 "
        "{%0,%1}, {%2,%3,%4,%5}, {%6,%7}, {%0,%1};"
        : "+r"(c[0]), "+r"(c[1])
        : "r"(a[0]), "r"(a[1]), "r"(a[2]), "r"(a[3]), "r"(b0), "r"(b1));
}
__device__ __forceinline__ void cp16(uint32_t dst, const void* src) {
    asm volatile("cp.async.cg.shared.global [%0], [%1], 16;" :: "r"(dst), "l"(src));
}
__device__ __forceinline__ void cp_commit() {
    asm volatile("cp.async.commit_group;" ::: "memory");
}
template <int N>
__device__ __forceinline__ void cp_wait() {
    asm volatile("cp.async.wait_group %0;" :: "n"(N) : "memory");
}
__device__ __forceinline__ uint32_t h2exp2(uint32_t x) {
    uint32_t r;
    asm("ex2.approx.f16x2 %0, %1;" : "=r"(r) : "r"(x));
    return r;
}

// ---------------------------------------------------------------------------
// batched fp32 -> fp16 convert
// ---------------------------------------------------------------------------
__global__ void __launch_bounds__(256)
cvt_f16_3(const float* __restrict__ s0, const float* __restrict__ s1,
          const float* __restrict__ s2, __half* __restrict__ d0,
          __half* __restrict__ d1, __half* __restrict__ d2, int n) {
    const int z = blockIdx.y;
    const float* s = z == 0 ? s0 : (z == 1 ? s1 : s2);
    __half* d = z == 0 ? d0 : (z == 1 ? d1 : d2);
    const int i = (blockIdx.x * 256 + threadIdx.x) * 8;
    if (i >= n) return;
    const float4 f0 = *(const float4*)(s + i);
    const float4 f1 = *(const float4*)(s + i + 4);
    __half2 h0 = __floats2half2_rn(f0.x, f0.y);
    __half2 h1 = __floats2half2_rn(f0.z, f0.w);
    __half2 h2 = __floats2half2_rn(f1.x, f1.y);
    __half2 h3 = __floats2half2_rn(f1.z, f1.w);
    uint4 o;
    o.x = *(uint32_t*)&h0; o.y = *(uint32_t*)&h1;
    o.z = *(uint32_t*)&h2; o.w = *(uint32_t*)&h3;
    *(uint4*)(d + i) = o;
}

__global__ void __launch_bounds__(256)
cvt_f16_4(const float* __restrict__ s0, const float* __restrict__ s1,
          const float* __restrict__ s2, const float* __restrict__ s3,
          __half* __restrict__ d0, __half* __restrict__ d1,
          __half* __restrict__ d2, __half* __restrict__ d3, int n) {
    const int z = blockIdx.y;
    const float* s = z == 0 ? s0 : (z == 1 ? s1 : (z == 2 ? s2 : s3));
    __half* d = z == 0 ? d0 : (z == 1 ? d1 : (z == 2 ? d2 : d3));
    const int i = (blockIdx.x * 256 + threadIdx.x) * 8;
    if (i >= n) return;
    const float4 f0 = *(const float4*)(s + i);
    const float4 f1 = *(const float4*)(s + i + 4);
    __half2 h0 = __floats2half2_rn(f0.x, f0.y);
    __half2 h1 = __floats2half2_rn(f0.z, f0.w);
    __half2 h2 = __floats2half2_rn(f1.x, f1.y);
    __half2 h3 = __floats2half2_rn(f1.z, f1.w);
    uint4 o;
    o.x = *(uint32_t*)&h0; o.y = *(uint32_t*)&h1;
    o.z = *(uint32_t*)&h2; o.w = *(uint32_t*)&h3;
    *(uint4*)(d + i) = o;
}

// ---------------------------------------------------------------------------
// GEMM core: 128x128 tile, 8 warps (warp 64x32), k-tile 64, 3-stage cp.async
// smem: A stages [3][128][72], B stages [3][128][72] -> 110592 B total
// ---------------------------------------------------------------------------
#define GLDS 72
#define GSTG (128 * GLDS * 2)          // 18432 B per operand per stage
#define GEMM_SMEM (6 * GSTG)           // 110592 B

__device__ __forceinline__ void gemm_core(const __half* __restrict__ Ag,
                                          const __half* __restrict__ Bg,
                                          uint32_t sA, uint32_t sB,
                                          float acc[4][4][4],
                                          int tid, int lane, int warp_m, int warp_n) {
    const int lr  = tid >> 1;            // 0..127
    const int lc0 = (tid & 1) * 32;      // 0 or 32 halves; 4 chunks of 8

    auto stage_load = [&](int st, int k0) {
        const uint32_t da = sA + st * GSTG + (lr * GLDS + lc0) * 2;
        const uint32_t db = sB + st * GSTG + (lr * GLDS + lc0) * 2;
        const __half* pa = Ag + (size_t)lr * DM + k0 + lc0;
        const __half* pb = Bg + (size_t)lr * DM + k0 + lc0;
        #pragma unroll
        for (int c = 0; c < 4; c++) {
            cp16(da + c * 16, pa + c * 8);
            cp16(db + c * 16, pb + c * 8);
        }
    };

    stage_load(0, 0);   cp_commit();
    stage_load(1, 64);  cp_commit();

    const int arow = warp_m * 64 + (lane & 15);
    const int acol = (lane >> 4) * 8;
    const int brow = warp_n * 32 + (lane & 7) + ((lane & 16) ? 8 : 0);
    const int bcol = ((lane >> 3) & 1) * 8;

    constexpr int NKT = DM / 64;  // 16
    for (int kt = 0; kt < NKT; ++kt) {
        cp_wait<1>();
        __syncthreads();

        const int st = kt % 3;
        const uint32_t ab = sA + st * GSTG;
        const uint32_t bb = sB + st * GSTG;
        #pragma unroll
        for (int s = 0; s < 4; s++) {
            uint32_t afr[4][4], bfr[4][2];
            #pragma unroll
            for (int mf = 0; mf < 4; mf++)
                ldsm_x4(afr[mf][0], afr[mf][1], afr[mf][2], afr[mf][3],
                        ab + ((arow + mf * 16) * GLDS + s * 16 + acol) * 2);
            #pragma unroll
            for (int np = 0; np < 2; np++)
                ldsm_x4(bfr[2 * np][0], bfr[2 * np][1], bfr[2 * np + 1][0], bfr[2 * np + 1][1],
                        bb + ((brow + np * 16) * GLDS + s * 16 + bcol) * 2);
            #pragma unroll
            for (int mf = 0; mf < 4; mf++)
                #pragma unroll
                for (int nf = 0; nf < 4; nf++)
                    mma16816(acc[mf][nf], afr[mf], bfr[nf][0], bfr[nf][1]);
        }

        // prefetch stage consumed at kt-1 (safe: barrier above ordered all reads)
        if (kt + 2 < NKT) stage_load((kt + 2) % 3, (kt + 2) * 64);
        cp_commit();
    }
}

// ---------------------------------------------------------------------------
// Combined QKV projection: blockIdx.z = 0(Q) / 1(K) / 2(V, transposed out)
// ---------------------------------------------------------------------------
__global__ void __launch_bounds__(256, 2)
proj_qkv(const __half* __restrict__ a0, const __half* __restrict__ a1,
         const __half* __restrict__ a2, const __half* __restrict__ w0,
         const __half* __restrict__ w1, const __half* __restrict__ w2,
         __half* __restrict__ c0, __half* __restrict__ c1, __half* __restrict__ c2,
         const float* __restrict__ bias0, const float* __restrict__ bias1,
         const float* __restrict__ bias2) {
    extern __shared__ __align__(16) char smg[];
    const uint32_t sA = smem_u32(smg);
    const uint32_t sB = sA + 3 * GSTG;

    const int tid  = threadIdx.x;
    const int lane = tid & 31, wid = tid >> 5;
    const int warp_m = wid & 1, warp_n = wid >> 1;
    const int m0 = blockIdx.y * 128, n0 = blockIdx.x * 128;
    const int z  = blockIdx.z;

    const __half* A = (z == 0 ? a0 : (z == 1 ? a1 : a2)) + (size_t)m0 * DM;
    const __half* B = (z == 0 ? w0 : (z == 1 ? w1 : w2)) + (size_t)n0 * DM;
    const float* bias = z == 0 ? bias0 : (z == 1 ? bias1 : bias2);
    const float scale = z == 0 ? QSCALE : 1.0f;

    float acc[4][4][4] = {};
    gemm_core(A, B, sA, sB, acc, tid, lane, warp_m, warp_n);

    const int g = lane >> 2, t4 = lane & 3;
    #pragma unroll
    for (int mf = 0; mf < 4; mf++) {
        #pragma unroll
        for (int nf = 0; nf < 4; nf++) {
            const int ncol = n0 + warp_n * 32 + nf * 8 + t4 * 2;
            const float b0 = bias[ncol], b1 = bias[ncol + 1];
            #pragma unroll
            for (int p = 0; p < 2; p++) {
                const int m = m0 + warp_m * 64 + mf * 16 + g + p * 8;
                const float v0 = (acc[mf][nf][p * 2 + 0] + b0) * scale;
                const float v1 = (acc[mf][nf][p * 2 + 1] + b1) * scale;
                if (z == 2) {
                    const size_t boff = (size_t)(m >> 11) * DM * SEQ;
                    const int s = m & (SEQ - 1);
                    c2[boff + (size_t)ncol * SEQ + s]       = (__half)v0;
                    c2[boff + (size_t)(ncol + 1) * SEQ + s] = (__half)v1;
                } else {
                    __half* dst = (z == 0 ? c0 : c1) + (size_t)m * DM + ncol;
                    __half2 h = __floats2half2_rn(v0, v1);
                    *(uint32_t*)dst = *(uint32_t*)&h;
                }
            }
        }
    }
}

// ---------------------------------------------------------------------------
// O projection
// ---------------------------------------------------------------------------
__global__ void __launch_bounds__(256, 2)
proj_o(const __half* __restrict__ A_, const __half* __restrict__ B_,
       float* __restrict__ C, const float* __restrict__ bias) {
    extern __shared__ __align__(16) char smg[];
    const uint32_t sA = smem_u32(smg);
    const uint32_t sB = sA + 3 * GSTG;

    const int tid  = threadIdx.x;
    const int lane = tid & 31, wid = tid >> 5;
    const int warp_m = wid & 1, warp_n = wid >> 1;
    const int m0 = blockIdx.y * 128, n0 = blockIdx.x * 128;

    float acc[4][4][4] = {};
    gemm_core(A_ + (size_t)m0 * DM, B_ + (size_t)n0 * DM, sA, sB, acc,
              tid, lane, warp_m, warp_n);

    const int g = lane >> 2, t4 = lane & 3;
    #pragma unroll
    for (int mf = 0; mf < 4; mf++) {
        #pragma unroll
        for (int nf = 0; nf < 4; nf++) {
            const int ncol = n0 + warp_n * 32 + nf * 8 + t4 * 2;
            const float b0 = bias[ncol], b1 = bias[ncol + 1];
            #pragma unroll
            for (int p = 0; p < 2; p++) {
                const int m = m0 + warp_m * 64 + mf * 16 + g + p * 8;
                *(float2*)(C + (size_t)m * DM + ncol) =
                    make_float2(acc[mf][nf][p * 2 + 0] + b0,
                                acc[mf][nf][p * 2 + 1] + b1);
            }
        }
    }
}

// ---------------------------------------------------------------------------
// Fused attention (R7 config: 8 warps x 16 q-rows — best measured).
// QK^T fp16-acc; P = ex2.f16x2; PV + normalizer fp32-acc.
// ---------------------------------------------------------------------------
#define LDK 72
#define KVB (64 * LDK * 2)

__global__ void __launch_bounds__(256, 2)
attn_fused(const __half* __restrict__ Qh, const __half* __restrict__ Kh,
           const __half* __restrict__ Vt, __half* __restrict__ Ah) {
    extern __shared__ __align__(16) __half sm[];
    __half* Qs = sm;
    const uint32_t ksBase = smem_u32(Qs + 128 * LDK);
    const uint32_t vsBase = ksBase + 2 * KVB;

    const int tid  = threadIdx.x;
    const int lane = tid & 31, wid = tid >> 5;
    const int h = blockIdx.y, b = blockIdx.z;
    const int q0 = blockIdx.x * 128;

    const __half* Qg = Qh + ((size_t)(b * SEQ + q0)) * DM + h * DHD;
    #pragma unroll
    for (int i = tid; i < 128 * 8; i += 256) {
        const int r = i >> 3, c8 = (i & 7) * 8;
        *(uint4*)&Qs[r * LDK + c8] = *(const uint4*)(Qg + (size_t)r * DM + c8);
    }

    const __half* Kg = Kh + ((size_t)b * SEQ) * DM + h * DHD;
    const __half* Vg = Vt + ((size_t)b * DM + h * DHD) * SEQ;
    const int lr = tid >> 2;
    const int lc = (tid & 3) * 16;

    auto load_kv = [&](int buf, int kv0) {
        const __half* ksrc = Kg + (size_t)(kv0 + lr) * DM + lc;
        const __half* vsrc = Vg + (size_t)lr * SEQ + kv0 + lc;
        const uint32_t kdst = ksBase + buf * KVB + (lr * LDK + lc) * 2;
        const uint32_t vdst = vsBase + buf * KVB + (lr * LDK + lc) * 2;
        cp16(kdst, ksrc);
        cp16(kdst + 16, ksrc + 8);
        cp16(vdst, vsrc);
        cp16(vdst + 16, vsrc + 8);
    };

    load_kv(0, 0);
    cp_commit();
    cp_wait<0>();
    __syncthreads();

    uint32_t qa[4][4];
    {
        const int row = wid * 16 + (lane & 15);
        #pragma unroll
        for (int ks = 0; ks < 4; ks++) {
            const int col = ks * 16 + (lane >> 4) * 8;
            ldsm_x4(qa[ks][0], qa[ks][1], qa[ks][2], qa[ks][3],
                    smem_u32(&Qs[row * LDK + col]));
        }
    }

    const uint32_t fragOff =
        (((lane & 7) + ((lane & 16) ? 8 : 0)) * LDK + ((lane >> 3) & 1) * 8) * 2;

    float o[8][4] = {};
    float lacc[4] = {};
    const uint32_t ONES = 0x3C003C00u;

    for (int t = 0; t < SEQ / 64; ++t) {
        const int cur = t & 1;
        if (t + 1 < SEQ / 64) {
            load_kv(cur ^ 1, (t + 1) * 64);
            cp_commit();
        }

        const uint32_t kb = ksBase + cur * KVB + fragOff;
        const uint32_t vb = vsBase + cur * KVB + fragOff;

        uint32_t sah[8][2] = {};
        #pragma unroll
        for (int ks = 0; ks < 4; ks++) {
            uint32_t bf[8][2];
            #pragma unroll
            for (int np = 0; np < 4; np++)
                ldsm_x4(bf[2 * np][0], bf[2 * np][1], bf[2 * np + 1][0], bf[2 * np + 1][1],
                        kb + np * (32 * LDK) + ks * 32);
            #pragma unroll
            for (int nf = 0; nf < 8; nf++)
                mma16816h(sah[nf], qa[ks], bf[nf][0], bf[nf][1]);
        }

        #pragma unroll
        for (int ks = 0; ks < 4; ks++) {
            uint32_t pa[4];
            pa[0] = h2exp2(sah[2 * ks][0]);
            pa[1] = h2exp2(sah[2 * ks][1]);
            pa[2] = h2exp2(sah[2 * ks + 1][0]);
            pa[3] = h2exp2(sah[2 * ks + 1][1]);

            uint32_t vf[8][2];
            #pragma unroll
            for (int np = 0; np < 4; np++)
                ldsm_x4(vf[2 * np][0], vf[2 * np][1], vf[2 * np + 1][0], vf[2 * np + 1][1],
                        vb + np * (32 * LDK) + ks * 32);
            #pragma unroll
            for (int nf = 0; nf < 8; nf++)
                mma16816(o[nf], pa, vf[nf][0], vf[nf][1]);
            mma16816(lacc, pa, ONES, ONES);
        }

        cp_wait<0>();
        __syncthreads();
    }

    const int g = lane >> 2, t4 = lane & 3;
    const float inv0 = 1.f / lacc[0];
    const float inv1 = 1.f / lacc[2];
    #pragma unroll
    for (int r = 0; r < 2; r++) {
        const float inv = r ? inv1 : inv0;
        const int m = q0 + wid * 16 + g + r * 8;
        __half* dst = Ah + ((size_t)(b * SEQ + m)) * DM + h * DHD;
        #pragma unroll
        for (int nf = 0; nf < 8; nf++) {
            __half2 hv = __floats2half2_rn(o[nf][2 * r] * inv, o[nf][2 * r + 1] * inv);
            *(uint32_t*)(dst + nf * 8 + t4 * 2) = *(uint32_t*)&hv;
        }
    }
}

// ---------------------------------------------------------------------------
extern "C" void kernel_launch(void* const* d_in, const int* in_sizes, int n_in,
                              void* d_out, int out_size) {
    const float* q  = (const float*)d_in[0];
    const float* k  = (const float*)d_in[1];
    const float* v  = (const float*)d_in[2];
    const float* Wq = (const float*)d_in[3];
    const float* bq = (const float*)d_in[4];
    const float* Wk = (const float*)d_in[5];
    const float* bk = (const float*)d_in[6];
    const float* Wv = (const float*)d_in[7];
    const float* bv = (const float*)d_in[8];
    const float* Wo = (const float*)d_in[9];
    const float* bo = (const float*)d_in[10];

    __half *qf, *kf, *vf, *Wqf, *Wkf, *Wvf, *Wof, *Qh, *Kh, *Vt, *Ah;
    cudaGetSymbolAddress((void**)&qf,  g_qf);
    cudaGetSymbolAddress((void**)&kf,  g_kf);
    cudaGetSymbolAddress((void**)&vf,  g_vf);
    cudaGetSymbolAddress((void**)&Wqf, g_Wqf);
    cudaGetSymbolAddress((void**)&Wkf, g_Wkf);
    cudaGetSymbolAddress((void**)&Wvf, g_Wvf);
    cudaGetSymbolAddress((void**)&Wof, g_Wof);
    cudaGetSymbolAddress((void**)&Qh,  g_Qh);
    cudaGetSymbolAddress((void**)&Kh,  g_Kh);
    cudaGetSymbolAddress((void**)&Vt,  g_Vt);
    cudaGetSymbolAddress((void**)&Ah,  g_Ah);

    const int NACT = NB * SEQ * DM;
    const int NW   = DM * DM;
    cvt_f16_3<<<dim3(NACT / 2048, 3), 256>>>(q, k, v, qf, kf, vf, NACT);
    cvt_f16_4<<<dim3(NW / 2048, 4), 256>>>(Wq, Wk, Wv, Wo, Wqf, Wkf, Wvf, Wof, NW);

    cudaFuncSetAttribute(proj_qkv, cudaFuncAttributeMaxDynamicSharedMemorySize, GEMM_SMEM);
    cudaFuncSetAttribute(proj_qkv, cudaFuncAttributePreferredSharedMemoryCarveout, 100);
    cudaFuncSetAttribute(proj_o, cudaFuncAttributeMaxDynamicSharedMemorySize, GEMM_SMEM);
    cudaFuncSetAttribute(proj_o, cudaFuncAttributePreferredSharedMemoryCarveout, 100);

    proj_qkv<<<dim3(DM / 128, (NB * SEQ) / 128, 3), 256, GEMM_SMEM>>>(
        qf, kf, vf, Wqf, Wkf, Wvf, Qh, Kh, Vt, bq, bk, bv);

    const int smem_attn = 128 * LDK * 2 + 4 * KVB;  // 55296
    cudaFuncSetAttribute(attn_fused, cudaFuncAttributeMaxDynamicSharedMemorySize, smem_attn);
    cudaFuncSetAttribute(attn_fused, cudaFuncAttributePreferredSharedMemoryCarveout, 100);
    attn_fused<<<dim3(SEQ / 128, NH, NB), 256, smem_attn>>>(Qh, Kh, Vt, Ah);

    proj_o<<<dim3(DM / 128, (NB * SEQ) / 128), 256, GEMM_SMEM>>>(
        Ah, Wof, (float*)d_out, bo);
}

// round 10
// speedup vs baseline: 1.0925x; 1.0925x over previous
#include <cuda_runtime.h>
#include <cuda_fp16.h>
#include <cstdint>

#define SEQ 2048
#define DM  1024
#define NB  2
#define NH  16
#define DHD 64

// 0.125 * log2(e)
#define QSCALE 0.1803368801111244f

// ---------------------------------------------------------------------------
// Scratch
// ---------------------------------------------------------------------------
__device__ __half g_qf[(size_t)NB * SEQ * DM];
__device__ __half g_kf[(size_t)NB * SEQ * DM];
__device__ __half g_vf[(size_t)NB * SEQ * DM];
__device__ __half g_Wqf[(size_t)DM * DM];
__device__ __half g_Wkf[(size_t)DM * DM];
__device__ __half g_Wvf[(size_t)DM * DM];
__device__ __half g_Wof[(size_t)DM * DM];
__device__ __half g_Qh[(size_t)NB * SEQ * DM];
__device__ __half g_Kh[(size_t)NB * SEQ * DM];
__device__ __half g_Vt[(size_t)NB * DM * SEQ];
__device__ __half g_Ah[(size_t)NB * SEQ * DM];

// ---------------------------------------------------------------------------
// PTX helpers
// ---------------------------------------------------------------------------
__device__ __forceinline__ uint32_t smem_u32(const void* p) {
    uint32_t a;
    asm("{ .reg .u64 t; cvta.to.shared.u64 t, %1; cvt.u32.u64 %0, t; }" : "=r"(a) : "l"(p));
    return a;
}
__device__ __forceinline__ void ldsm_x4(uint32_t& r0, uint32_t& r1, uint32_t& r2,
                                        uint32_t& r3, uint32_t addr) {
    asm volatile("ldmatrix.sync.aligned.m8n8.x4.shared.b16 {%0,%1,%2,%3}, [%4];"
                 : "=r"(r0), "=r"(r1), "=r"(r2), "=r"(r3) : "r"(addr));
}
__device__ __forceinline__ void mma16816(float* c, const uint32_t* a,
                                         uint32_t b0, uint32_t b1) {
    asm volatile(
        "mma.sync.aligned.m16n8k16.row.col.f32.f16.f16.f32 "
        "{%0,%1,%2,%3}, {%4,%5,%6,%7}, {%8,%9}, {%0,%1,%2,%3};"
        : "+f"(c[0]), "+f"(c[1]), "+f"(c[2]), "+f"(c[3])
        : "r"(a[0]), "r"(a[1]), "r"(a[2]), "r"(a[3]), "r"(b0), "r"(b1));
}
__device__ __forceinline__ void mma16816h(uint32_t* c, const uint32_t* a,
                                          uint32_t b0, uint32_t b1) {
    asm volatile(
        "mma.sync.aligned.m16n8k16.row.col.f16.f16.f16.f16 "
        "{%0,%1}, {%2,%3,%4,%5}, {%6,%7}, {%0,%1};"
        : "+r"(c[0]), "+r"(c[1])
        : "r"(a[0]), "r"(a[1]), "r"(a[2]), "r"(a[3]), "r"(b0), "r"(b1));
}
__device__ __forceinline__ void cp16(uint32_t dst, const void* src) {
    asm volatile("cp.async.cg.shared.global [%0], [%1], 16;" :: "r"(dst), "l"(src));
}
__device__ __forceinline__ void cp_commit() {
    asm volatile("cp.async.commit_group;" ::: "memory");
}
template <int N>
__device__ __forceinline__ void cp_wait() {
    asm volatile("cp.async.wait_group %0;" :: "n"(N) : "memory");
}
__device__ __forceinline__ uint32_t h2exp2(uint32_t x) {
    uint32_t r;
    asm("ex2.approx.f16x2 %0, %1;" : "=r"(r) : "r"(x));
    return r;
}

// ---------------------------------------------------------------------------
// batched fp32 -> fp16 convert
// ---------------------------------------------------------------------------
__global__ void __launch_bounds__(256)
cvt_f16_3(const float* __restrict__ s0, const float* __restrict__ s1,
          const float* __restrict__ s2, __half* __restrict__ d0,
          __half* __restrict__ d1, __half* __restrict__ d2, int n) {
    const int z = blockIdx.y;
    const float* s = z == 0 ? s0 : (z == 1 ? s1 : s2);
    __half* d = z == 0 ? d0 : (z == 1 ? d1 : d2);
    const int i = (blockIdx.x * 256 + threadIdx.x) * 8;
    if (i >= n) return;
    const float4 f0 = *(const float4*)(s + i);
    const float4 f1 = *(const float4*)(s + i + 4);
    __half2 h0 = __floats2half2_rn(f0.x, f0.y);
    __half2 h1 = __floats2half2_rn(f0.z, f0.w);
    __half2 h2 = __floats2half2_rn(f1.x, f1.y);
    __half2 h3 = __floats2half2_rn(f1.z, f1.w);
    uint4 o;
    o.x = *(uint32_t*)&h0; o.y = *(uint32_t*)&h1;
    o.z = *(uint32_t*)&h2; o.w = *(uint32_t*)&h3;
    *(uint4*)(d + i) = o;
}

__global__ void __launch_bounds__(256)
cvt_f16_4(const float* __restrict__ s0, const float* __restrict__ s1,
          const float* __restrict__ s2, const float* __restrict__ s3,
          __half* __restrict__ d0, __half* __restrict__ d1,
          __half* __restrict__ d2, __half* __restrict__ d3, int n) {
    const int z = blockIdx.y;
    const float* s = z == 0 ? s0 : (z == 1 ? s1 : (z == 2 ? s2 : s3));
    __half* d = z == 0 ? d0 : (z == 1 ? d1 : (z == 2 ? d2 : d3));
    const int i = (blockIdx.x * 256 + threadIdx.x) * 8;
    if (i >= n) return;
    const float4 f0 = *(const float4*)(s + i);
    const float4 f1 = *(const float4*)(s + i + 4);
    __half2 h0 = __floats2half2_rn(f0.x, f0.y);
    __half2 h1 = __floats2half2_rn(f0.z, f0.w);
    __half2 h2 = __floats2half2_rn(f1.x, f1.y);
    __half2 h3 = __floats2half2_rn(f1.z, f1.w);
    uint4 o;
    o.x = *(uint32_t*)&h0; o.y = *(uint32_t*)&h1;
    o.z = *(uint32_t*)&h2; o.w = *(uint32_t*)&h3;
    *(uint4*)(d + i) = o;
}

// ---------------------------------------------------------------------------
// GEMM core (R7 config: 128x128 tile, 8 warps, k-tile 32, 4-stage cp.async)
// ---------------------------------------------------------------------------
#define GLDS 40
#define GSTG (128 * GLDS * 2)
#define GEMM_SMEM (8 * GSTG)           // 81920 B

__device__ __forceinline__ void gemm_core(const __half* __restrict__ Ag,
                                          const __half* __restrict__ Bg,
                                          uint32_t sA, uint32_t sB,
                                          float acc[4][4][4],
                                          int tid, int lane, int warp_m, int warp_n) {
    const int lr  = tid >> 1;
    const int lc0 = (tid & 1) * 16;

    auto stage_load = [&](int st, int k0) {
        const uint32_t da = sA + st * GSTG + (lr * GLDS + lc0) * 2;
        const uint32_t db = sB + st * GSTG + (lr * GLDS + lc0) * 2;
        const __half* pa = Ag + (size_t)lr * DM + k0 + lc0;
        const __half* pb = Bg + (size_t)lr * DM + k0 + lc0;
        cp16(da,      pa);
        cp16(da + 16, pa + 8);
        cp16(db,      pb);
        cp16(db + 16, pb + 8);
    };

    stage_load(0, 0);  cp_commit();
    stage_load(1, 32); cp_commit();
    stage_load(2, 64); cp_commit();

    const int arow = warp_m * 64 + (lane & 15);
    const int acol = (lane >> 4) * 8;
    const int brow = warp_n * 32 + (lane & 7) + ((lane & 16) ? 8 : 0);
    const int bcol = ((lane >> 3) & 1) * 8;

    constexpr int NKT = DM / 32;
    for (int kt = 0; kt < NKT; ++kt) {
        cp_wait<2>();
        __syncthreads();

        const int st = kt & 3;
        const uint32_t ab = sA + st * GSTG;
        const uint32_t bb = sB + st * GSTG;
        #pragma unroll
        for (int s = 0; s < 2; s++) {
            uint32_t afr[4][4], bfr[4][2];
            #pragma unroll
            for (int mf = 0; mf < 4; mf++)
                ldsm_x4(afr[mf][0], afr[mf][1], afr[mf][2], afr[mf][3],
                        ab + ((arow + mf * 16) * GLDS + s * 16 + acol) * 2);
            #pragma unroll
            for (int np = 0; np < 2; np++)
                ldsm_x4(bfr[2 * np][0], bfr[2 * np][1], bfr[2 * np + 1][0], bfr[2 * np + 1][1],
                        bb + ((brow + np * 16) * GLDS + s * 16 + bcol) * 2);
            #pragma unroll
            for (int mf = 0; mf < 4; mf++)
                #pragma unroll
                for (int nf = 0; nf < 4; nf++)
                    mma16816(acc[mf][nf], afr[mf], bfr[nf][0], bfr[nf][1]);
        }

        if (kt + 3 < NKT) stage_load((kt + 3) & 3, (kt + 3) * 32);
        cp_commit();
    }
}

// ---------------------------------------------------------------------------
// Combined QKV projection: blockIdx.z = 0(Q) / 1(K) / 2(V, transposed out).
// z==2 stages the tile through smem to make Vt writes coalesced.
// ---------------------------------------------------------------------------
#define TPAD 136   // transpose tile row stride (halves)

__global__ void __launch_bounds__(256, 2)
proj_qkv(const __half* __restrict__ a0, const __half* __restrict__ a1,
         const __half* __restrict__ a2, const __half* __restrict__ w0,
         const __half* __restrict__ w1, const __half* __restrict__ w2,
         __half* __restrict__ c0, __half* __restrict__ c1, __half* __restrict__ c2,
         const float* __restrict__ bias0, const float* __restrict__ bias1,
         const float* __restrict__ bias2) {
    extern __shared__ __align__(16) char smg[];
    const uint32_t sA = smem_u32(smg);
    const uint32_t sB = sA + 4 * GSTG;

    const int tid  = threadIdx.x;
    const int lane = tid & 31, wid = tid >> 5;
    const int warp_m = wid & 1, warp_n = wid >> 1;
    const int m0 = blockIdx.y * 128, n0 = blockIdx.x * 128;
    const int z  = blockIdx.z;

    const __half* A = (z == 0 ? a0 : (z == 1 ? a1 : a2)) + (size_t)m0 * DM;
    const __half* B = (z == 0 ? w0 : (z == 1 ? w1 : w2)) + (size_t)n0 * DM;
    const float* bias = z == 0 ? bias0 : (z == 1 ? bias1 : bias2);
    const float scale = z == 0 ? QSCALE : 1.0f;

    float acc[4][4][4] = {};
    gemm_core(A, B, sA, sB, acc, tid, lane, warp_m, warp_n);

    const int g = lane >> 2, t4 = lane & 3;

    if (z == 2) {
        // ---- transpose epilogue: acc -> smem T[n][m] -> coalesced Vt rows ----
        __half* T = (__half*)smg;   // [128][TPAD], 34816 B (reuses GEMM stages)
        __syncthreads();            // all warps done reading GEMM smem
        #pragma unroll
        for (int mf = 0; mf < 4; mf++) {
            #pragma unroll
            for (int nf = 0; nf < 4; nf++) {
                const int nl = warp_n * 32 + nf * 8 + t4 * 2;
                const float b0 = bias[n0 + nl], b1 = bias[n0 + nl + 1];
                #pragma unroll
                for (int p = 0; p < 2; p++) {
                    const int ml = warp_m * 64 + mf * 16 + g + p * 8;
                    T[nl * TPAD + ml]       = (__half)(acc[mf][nf][p * 2 + 0] + b0);
                    T[(nl + 1) * TPAD + ml] = (__half)(acc[mf][nf][p * 2 + 1] + b1);
                }
            }
        }
        __syncthreads();
        // write out: Vt[(b*DM + n0 + r) * SEQ + (m0&2047) + c], coalesced 16B
        const int b = m0 >> 11;
        const int s0 = m0 & (SEQ - 1);
        __half* dstBase = c2 + ((size_t)b * DM + n0) * SEQ + s0;
        #pragma unroll
        for (int k = 0; k < 8; k++) {
            const int idx = tid + k * 256;        // 2048 chunks = 128 rows x 16
            const int r  = idx >> 4;
            const int c8 = (idx & 15) * 8;
            *(uint4*)(dstBase + (size_t)r * SEQ + c8) = *(const uint4*)&T[r * TPAD + c8];
        }
    } else {
        #pragma unroll
        for (int mf = 0; mf < 4; mf++) {
            #pragma unroll
            for (int nf = 0; nf < 4; nf++) {
                const int ncol = n0 + warp_n * 32 + nf * 8 + t4 * 2;
                const float b0 = bias[ncol], b1 = bias[ncol + 1];
                #pragma unroll
                for (int p = 0; p < 2; p++) {
                    const int m = m0 + warp_m * 64 + mf * 16 + g + p * 8;
                    const float v0 = (acc[mf][nf][p * 2 + 0] + b0) * scale;
                    const float v1 = (acc[mf][nf][p * 2 + 1] + b1) * scale;
                    __half* dst = (z == 0 ? c0 : c1) + (size_t)m * DM + ncol;
                    __half2 h = __floats2half2_rn(v0, v1);
                    *(uint32_t*)dst = *(uint32_t*)&h;
                }
            }
        }
    }
}

// ---------------------------------------------------------------------------
// O projection
// ---------------------------------------------------------------------------
__global__ void __launch_bounds__(256, 2)
proj_o(const __half* __restrict__ A_, const __half* __restrict__ B_,
       float* __restrict__ C, const float* __restrict__ bias) {
    extern __shared__ __align__(16) char smg[];
    const uint32_t sA = smem_u32(smg);
    const uint32_t sB = sA + 4 * GSTG;

    const int tid  = threadIdx.x;
    const int lane = tid & 31, wid = tid >> 5;
    const int warp_m = wid & 1, warp_n = wid >> 1;
    const int m0 = blockIdx.y * 128, n0 = blockIdx.x * 128;

    float acc[4][4][4] = {};
    gemm_core(A_ + (size_t)m0 * DM, B_ + (size_t)n0 * DM, sA, sB, acc,
              tid, lane, warp_m, warp_n);

    const int g = lane >> 2, t4 = lane & 3;
    #pragma unroll
    for (int mf = 0; mf < 4; mf++) {
        #pragma unroll
        for (int nf = 0; nf < 4; nf++) {
            const int ncol = n0 + warp_n * 32 + nf * 8 + t4 * 2;
            const float b0 = bias[ncol], b1 = bias[ncol + 1];
            #pragma unroll
            for (int p = 0; p < 2; p++) {
                const int m = m0 + warp_m * 64 + mf * 16 + g + p * 8;
                *(float2*)(C + (size_t)m * DM + ncol) =
                    make_float2(acc[mf][nf][p * 2 + 0] + b0,
                                acc[mf][nf][p * 2 + 1] + b1);
            }
        }
    }
}

// ---------------------------------------------------------------------------
// Fused attention (R7 config: 8 warps x 16 q-rows — measured optimum).
// ---------------------------------------------------------------------------
#define LDK 72
#define KVB (64 * LDK * 2)

__global__ void __launch_bounds__(256, 2)
attn_fused(const __half* __restrict__ Qh, const __half* __restrict__ Kh,
           const __half* __restrict__ Vt, __half* __restrict__ Ah) {
    extern __shared__ __align__(16) __half sm[];
    __half* Qs = sm;
    const uint32_t ksBase = smem_u32(Qs + 128 * LDK);
    const uint32_t vsBase = ksBase + 2 * KVB;

    const int tid  = threadIdx.x;
    const int lane = tid & 31, wid = tid >> 5;
    const int h = blockIdx.y, b = blockIdx.z;
    const int q0 = blockIdx.x * 128;

    const __half* Qg = Qh + ((size_t)(b * SEQ + q0)) * DM + h * DHD;
    #pragma unroll
    for (int i = tid; i < 128 * 8; i += 256) {
        const int r = i >> 3, c8 = (i & 7) * 8;
        *(uint4*)&Qs[r * LDK + c8] = *(const uint4*)(Qg + (size_t)r * DM + c8);
    }

    const __half* Kg = Kh + ((size_t)b * SEQ) * DM + h * DHD;
    const __half* Vg = Vt + ((size_t)b * DM + h * DHD) * SEQ;
    const int lr = tid >> 2;
    const int lc = (tid & 3) * 16;

    auto load_kv = [&](int buf, int kv0) {
        const __half* ksrc = Kg + (size_t)(kv0 + lr) * DM + lc;
        const __half* vsrc = Vg + (size_t)lr * SEQ + kv0 + lc;
        const uint32_t kdst = ksBase + buf * KVB + (lr * LDK + lc) * 2;
        const uint32_t vdst = vsBase + buf * KVB + (lr * LDK + lc) * 2;
        cp16(kdst, ksrc);
        cp16(kdst + 16, ksrc + 8);
        cp16(vdst, vsrc);
        cp16(vdst + 16, vsrc + 8);
    };

    load_kv(0, 0);
    cp_commit();
    cp_wait<0>();
    __syncthreads();

    uint32_t qa[4][4];
    {
        const int row = wid * 16 + (lane & 15);
        #pragma unroll
        for (int ks = 0; ks < 4; ks++) {
            const int col = ks * 16 + (lane >> 4) * 8;
            ldsm_x4(qa[ks][0], qa[ks][1], qa[ks][2], qa[ks][3],
                    smem_u32(&Qs[row * LDK + col]));
        }
    }

    const uint32_t fragOff =
        (((lane & 7) + ((lane & 16) ? 8 : 0)) * LDK + ((lane >> 3) & 1) * 8) * 2;

    float o[8][4] = {};
    float lacc[4] = {};
    const uint32_t ONES = 0x3C003C00u;

    for (int t = 0; t < SEQ / 64; ++t) {
        const int cur = t & 1;
        if (t + 1 < SEQ / 64) {
            load_kv(cur ^ 1, (t + 1) * 64);
            cp_commit();
        }

        const uint32_t kb = ksBase + cur * KVB + fragOff;
        const uint32_t vb = vsBase + cur * KVB + fragOff;

        uint32_t sah[8][2] = {};
        #pragma unroll
        for (int ks = 0; ks < 4; ks++) {
            uint32_t bf[8][2];
            #pragma unroll
            for (int np = 0; np < 4; np++)
                ldsm_x4(bf[2 * np][0], bf[2 * np][1], bf[2 * np + 1][0], bf[2 * np + 1][1],
                        kb + np * (32 * LDK) + ks * 32);
            #pragma unroll
            for (int nf = 0; nf < 8; nf++)
                mma16816h(sah[nf], qa[ks], bf[nf][0], bf[nf][1]);
        }

        #pragma unroll
        for (int ks = 0; ks < 4; ks++) {
            uint32_t pa[4];
            pa[0] = h2exp2(sah[2 * ks][0]);
            pa[1] = h2exp2(sah[2 * ks][1]);
            pa[2] = h2exp2(sah[2 * ks + 1][0]);
            pa[3] = h2exp2(sah[2 * ks + 1][1]);

            uint32_t vf[8][2];
            #pragma unroll
            for (int np = 0; np < 4; np++)
                ldsm_x4(vf[2 * np][0], vf[2 * np][1], vf[2 * np + 1][0], vf[2 * np + 1][1],
                        vb + np * (32 * LDK) + ks * 32);
            #pragma unroll
            for (int nf = 0; nf < 8; nf++)
                mma16816(o[nf], pa, vf[nf][0], vf[nf][1]);
            mma16816(lacc, pa, ONES, ONES);
        }

        cp_wait<0>();
        __syncthreads();
    }

    const int g = lane >> 2, t4 = lane & 3;
    const float inv0 = 1.f / lacc[0];
    const float inv1 = 1.f / lacc[2];
    #pragma unroll
    for (int r = 0; r < 2; r++) {
        const float inv = r ? inv1 : inv0;
        const int m = q0 + wid * 16 + g + r * 8;
        __half* dst = Ah + ((size_t)(b * SEQ + m)) * DM + h * DHD;
        #pragma unroll
        for (int nf = 0; nf < 8; nf++) {
            __half2 hv = __floats2half2_rn(o[nf][2 * r] * inv, o[nf][2 * r + 1] * inv);
            *(uint32_t*)(dst + nf * 8 + t4 * 2) = *(uint32_t*)&hv;
        }
    }
}

// ---------------------------------------------------------------------------
extern "C" void kernel_launch(void* const* d_in, const int* in_sizes, int n_in,
                              void* d_out, int out_size) {
    const float* q  = (const float*)d_in[0];
    const float* k  = (const float*)d_in[1];
    const float* v  = (const float*)d_in[2];
    const float* Wq = (const float*)d_in[3];
    const float* bq = (const float*)d_in[4];
    const float* Wk = (const float*)d_in[5];
    const float* bk = (const float*)d_in[6];
    const float* Wv = (const float*)d_in[7];
    const float* bv = (const float*)d_in[8];
    const float* Wo = (const float*)d_in[9];
    const float* bo = (const float*)d_in[10];

    __half *qf, *kf, *vf, *Wqf, *Wkf, *Wvf, *Wof, *Qh, *Kh, *Vt, *Ah;
    cudaGetSymbolAddress((void**)&qf,  g_qf);
    cudaGetSymbolAddress((void**)&kf,  g_kf);
    cudaGetSymbolAddress((void**)&vf,  g_vf);
    cudaGetSymbolAddress((void**)&Wqf, g_Wqf);
    cudaGetSymbolAddress((void**)&Wkf, g_Wkf);
    cudaGetSymbolAddress((void**)&Wvf, g_Wvf);
    cudaGetSymbolAddress((void**)&Wof, g_Wof);
    cudaGetSymbolAddress((void**)&Qh,  g_Qh);
    cudaGetSymbolAddress((void**)&Kh,  g_Kh);
    cudaGetSymbolAddress((void**)&Vt,  g_Vt);
    cudaGetSymbolAddress((void**)&Ah,  g_Ah);

    const int NACT = NB * SEQ * DM;
    const int NW   = DM * DM;
    cvt_f16_3<<<dim3(NACT / 2048, 3), 256>>>(q, k, v, qf, kf, vf, NACT);
    cvt_f16_4<<<dim3(NW / 2048, 4), 256>>>(Wq, Wk, Wv, Wo, Wqf, Wkf, Wvf, Wof, NW);

    cudaFuncSetAttribute(proj_qkv, cudaFuncAttributeMaxDynamicSharedMemorySize, GEMM_SMEM);
    cudaFuncSetAttribute(proj_qkv, cudaFuncAttributePreferredSharedMemoryCarveout, 100);
    cudaFuncSetAttribute(proj_o, cudaFuncAttributeMaxDynamicSharedMemorySize, GEMM_SMEM);
    cudaFuncSetAttribute(proj_o, cudaFuncAttributePreferredSharedMemoryCarveout, 100);

    proj_qkv<<<dim3(DM / 128, (NB * SEQ) / 128, 3), 256, GEMM_SMEM>>>(
        qf, kf, vf, Wqf, Wkf, Wvf, Qh, Kh, Vt, bq, bk, bv);

    const int smem_attn = 128 * LDK * 2 + 4 * KVB;  // 55296
    cudaFuncSetAttribute(attn_fused, cudaFuncAttributeMaxDynamicSharedMemorySize, smem_attn);
    cudaFuncSetAttribute(attn_fused, cudaFuncAttributePreferredSharedMemoryCarveout, 100);
    attn_fused<<<dim3(SEQ / 128, NH, NB), 256, smem_attn>>>(Qh, Kh, Vt, Ah);

    proj_o<<<dim3(DM / 128, (NB * SEQ) / 128), 256, GEMM_SMEM>>>(
        Ah, Wof, (float*)d_out, bo);
}